// round 5
// baseline (speedup 1.0000x reference)
#include <cuda_runtime.h>
#include <cuda_bf16.h>
#include <math.h>
#include <stdint.h>

#define L 4
#define NN 40000
#define D 128
#define KD 16
#define NE 320000
#define MROWS (L*NN)                 // 160000
#define SLICE ((size_t)NN*(size_t)D) // 5,120,000
#define VST 132                      // LN staging row stride (floats)
#define AST 136                      // A smem row stride (bf16 elems)
#define BST 136                      // B smem row stride (bf16 elems, n-major)

// dynamic smem: Ah(64*AST) Al(64*AST) Bh(128*BST) Bl(128*BST) bf16
#define SMEM_GEMM ((64*AST*2 + 128*BST*2) * 2)   // 104448 bytes

typedef unsigned long long ull;

// ---------------- packed fp32x2 helpers (used by k_weights) ----------------
__device__ __forceinline__ ull pack2(float lo, float hi) {
    ull r; asm("mov.b64 %0, {%1,%2};" : "=l"(r) : "f"(lo), "f"(hi)); return r;
}
__device__ __forceinline__ void fma2(ull& d, ull a, ull b) {
    asm("fma.rn.f32x2 %0, %1, %2, %0;" : "+l"(d) : "l"(a), "l"(b));
}
__device__ __forceinline__ float2 unp2(ull v) {
    float2 r; asm("mov.b64 {%0,%1}, %2;" : "=f"(r.x), "=f"(r.y) : "l"(v)); return r;
}

// ---------------- warp mma m16n8k16 bf16 ----------------
__device__ __forceinline__ void mma16816(float c[4], const unsigned a[4], const unsigned b[2]) {
    asm volatile("mma.sync.aligned.m16n8k16.row.col.f32.bf16.bf16.f32 "
        "{%0,%1,%2,%3},{%4,%5,%6,%7},{%8,%9},{%0,%1,%2,%3};"
        : "+f"(c[0]), "+f"(c[1]), "+f"(c[2]), "+f"(c[3])
        : "r"(a[0]), "r"(a[1]), "r"(a[2]), "r"(a[3]), "r"(b[0]), "r"(b[1]));
}

// ---------------- scratch (static device memory; no allocations) ----------------
static __device__ float g_S1[(size_t)L*NN*D];   // spmm(vals, x)          [L,N,D]
static __device__ float g_S2[(size_t)L*NN*D];   // spmm(vals, S1)         [L,N,D]
static __device__ float g_X [(size_t)L*NN*D];   // x + 0.5 S1 + 0.25 S2   [L,N,D]
static __device__ float g_h [(size_t)L*NN*D];   // sage_out+attn_out      [L,N,D]
static __device__ float g_w [MROWS];            // retention weights      [L*N]
static __device__ int   g_rowptr[NN+1];
static __device__ int   g_cnt[NN];
static __device__ int   g_cur[NN];
static __device__ int   g_ecol[NE];
static __device__ float g_eval[NE];

// ---------------- CSR build ----------------
__global__ void k_zero_counts() {
    int i = blockIdx.x*blockDim.x + threadIdx.x;
    if (i < NN) { g_cnt[i] = 0; g_cur[i] = 0; }
}

__global__ void k_hist(const int* __restrict__ rows) {
    int e = blockIdx.x*blockDim.x + threadIdx.x;
    if (e < NE) atomicAdd(&g_cnt[rows[e]], 1);
}

__global__ void k_scan() {
    __shared__ int sh[1024];
    int tid = threadIdx.x;
    int run = 0;
    const int TILES = (NN + 1023) / 1024;
    for (int t = 0; t < TILES; ++t) {
        int i = t*1024 + tid;
        int v = (i < NN) ? g_cnt[i] : 0;
        sh[tid] = v;
        __syncthreads();
        for (int off = 1; off < 1024; off <<= 1) {
            int add = (tid >= off) ? sh[tid - off] : 0;
            __syncthreads();
            sh[tid] += add;
            __syncthreads();
        }
        if (i < NN) g_rowptr[i] = run + sh[tid] - v;   // exclusive
        run += sh[1023];
        __syncthreads();
    }
    if (tid == 0) g_rowptr[NN] = run;
}

__global__ void k_scatter(const int* __restrict__ rows, const int* __restrict__ cols,
                          const float* __restrict__ vals) {
    int e = blockIdx.x*blockDim.x + threadIdx.x;
    if (e < NE) {
        int r = rows[e];
        int p = atomicAdd(&g_cur[r], 1);
        int idx = g_rowptr[r] + p;
        g_ecol[idx] = cols[e];
        g_eval[idx] = vals[e];
    }
}

// ---------------- SPMM ----------------
__global__ __launch_bounds__(128) void k_spmm(const float* __restrict__ x, int stage) {
    const float* __restrict__ in  = (stage == 0) ? x    : (const float*)g_S1;
    float*       __restrict__ out = (stage == 0) ? g_S1 : g_S2;
    int r = blockIdx.x;
    int d = threadIdx.x;
    int s  = g_rowptr[r];
    int e2 = g_rowptr[r+1];
    float a0 = 0.f, a1 = 0.f, a2 = 0.f, a3 = 0.f;
    for (int i = s; i < e2; ++i) {
        int   c = g_ecol[i];
        float v = g_eval[i];
        const float* p = in + (size_t)c*D + d;
        a0 += v * p[0];
        a1 += v * p[SLICE];
        a2 += v * p[2*SLICE];
        a3 += v * p[3*SLICE];
    }
    size_t o = (size_t)r*D + d;
    out[o]           = a0;
    out[o +   SLICE] = a1;
    out[o + 2*SLICE] = a2;
    out[o + 3*SLICE] = a3;
    if (stage == 1) {
        g_X[o]           = x[o]           + 0.5f*in[o]           + 0.25f*a0;
        g_X[o+  SLICE]   = x[o+  SLICE]   + 0.5f*in[o+  SLICE]   + 0.25f*a1;
        g_X[o+2*SLICE]   = x[o+2*SLICE]   + 0.5f*in[o+2*SLICE]   + 0.25f*a2;
        g_X[o+3*SLICE]   = x[o+3*SLICE]   + 0.5f*in[o+3*SLICE]   + 0.25f*a3;
    }
}

// ---------------- retention weights (scalar, proven) ----------------
__global__ __launch_bounds__(256) void k_weights(const float* __restrict__ x,
                                                 const float* __restrict__ keyW,
                                                 const float* __restrict__ qryW) {
    __shared__ __align__(16) float Kw[D*KD];
    __shared__ __align__(16) float Qw[D*KD];
    __shared__ float Zs[32*129];
    __shared__ float wsum[256];
    int tid  = threadIdx.x;
    for (int i = tid; i < D*KD; i += 256) { Kw[i] = keyW[i]; Qw[i] = qryW[i]; }
    int row  = tid & 127;
    int half = tid >> 7;
    size_t m0 = (size_t)blockIdx.x * 128;
    int kb = half * 8;
    float wacc = 0.f;
    #pragma unroll
    for (int t = 0; t < 3; ++t) {
        const float* src = (t == 0) ? x : (t == 1) ? (const float*)g_S1 : (const float*)g_S2;
        float sc = (t == 0) ? 1.f : (t == 1) ? 0.5f : 0.25f;
        ull aK[4] = {0,0,0,0};
        ull aQ[4] = {0,0,0,0};
        for (int dc = 0; dc < D; dc += 32) {
            __syncthreads();
            for (int i = tid; i < 128*32; i += 256) {
                int dd = i & 31, rr = i >> 5;
                Zs[dd*129 + rr] = sc * src[(m0 + rr)*(size_t)D + dc + dd];
            }
            __syncthreads();
            #pragma unroll
            for (int dd = 0; dd < 32; ++dd) {
                float zv = Zs[dd*129 + row];
                ull zp = pack2(zv, zv);
                const ulonglong2* kp = (const ulonglong2*)&Kw[(dc + dd)*KD + kb];
                const ulonglong2* qp = (const ulonglong2*)&Qw[(dc + dd)*KD + kb];
                ulonglong2 k0 = kp[0], k1 = kp[1];
                ulonglong2 q0 = qp[0], q1 = qp[1];
                fma2(aK[0], zp, k0.x); fma2(aK[1], zp, k0.y);
                fma2(aK[2], zp, k1.x); fma2(aK[3], zp, k1.y);
                fma2(aQ[0], zp, q0.x); fma2(aQ[1], zp, q0.y);
                fma2(aQ[2], zp, q1.x); fma2(aQ[3], zp, q1.y);
            }
        }
        float p = 0.f;
        #pragma unroll
        for (int k = 0; k < 4; ++k) {
            float2 fk = unp2(aK[k]), fq = unp2(aQ[k]);
            p += fk.x*fq.x + fk.y*fq.y;
        }
        wacc += p;
    }
    wsum[tid] = wacc;
    __syncthreads();
    if (half == 0) g_w[m0 + row] = (wacc + wsum[tid + 128]) * (1.f/16.f);
}

// ---------------- bf16-split tensor-core GEMM stage ----------------
// acc += A[m0:m0+64, 0:128] @ B[128,128] with A=Ah+Al, B=Bh+Bl (bf16 splits):
// passes Ah@Bh, Al@Bh, Ah@Bl. 256 threads = 8 warps in 2(m) x 4(n); warp tile 32x32.
__device__ __forceinline__ void mma_stage(const float* __restrict__ Agl,
                                          const float* __restrict__ Bgl,
                                          size_t m0, int tid,
                                          __nv_bfloat16* Ah, __nv_bfloat16* Al,
                                          __nv_bfloat16* Bh, __nv_bfloat16* Bl,
                                          float acc[2][4][4]) {
    __syncthreads();
    // --- A tile convert: 64x128 fp32 -> Ah/Al bf16 ---
    {
        const float4* A4 = (const float4*)Agl;
        #pragma unroll
        for (int i = tid; i < 64*32; i += 256) {
            int r = i >> 5, c4 = i & 31;
            float4 v = A4[(m0 + r)*32 + c4];
            __nv_bfloat16 h0 = __float2bfloat16(v.x), h1 = __float2bfloat16(v.y);
            __nv_bfloat16 h2 = __float2bfloat16(v.z), h3 = __float2bfloat16(v.w);
            __nv_bfloat16 l0 = __float2bfloat16(v.x - __bfloat162float(h0));
            __nv_bfloat16 l1 = __float2bfloat16(v.y - __bfloat162float(h1));
            __nv_bfloat16 l2 = __float2bfloat16(v.z - __bfloat162float(h2));
            __nv_bfloat16 l3 = __float2bfloat16(v.w - __bfloat162float(h3));
            __nv_bfloat162* dh = (__nv_bfloat162*)&Ah[r*AST + c4*4];
            dh[0] = __halves2bfloat162(h0, h1);
            dh[1] = __halves2bfloat162(h2, h3);
            __nv_bfloat162* dl = (__nv_bfloat162*)&Al[r*AST + c4*4];
            dl[0] = __halves2bfloat162(l0, l1);
            dl[1] = __halves2bfloat162(l2, l3);
        }
        // --- B convert + transpose: [k][n] fp32 -> Bh/Bl [n][k] bf16 ---
        const float4* B4 = (const float4*)Bgl;
        #pragma unroll
        for (int i = tid; i < 128*32; i += 256) {
            int k = i >> 5, n4 = (i & 31)*4;
            float4 v = B4[i];
            float f[4] = {v.x, v.y, v.z, v.w};
            #pragma unroll
            for (int e = 0; e < 4; ++e) {
                __nv_bfloat16 h = __float2bfloat16(f[e]);
                __nv_bfloat16 l = __float2bfloat16(f[e] - __bfloat162float(h));
                Bh[(n4+e)*BST + k] = h;
                Bl[(n4+e)*BST + k] = l;
            }
        }
    }
    __syncthreads();
    int lane = tid & 31, w = tid >> 5;
    int wm = w >> 2, wn = w & 3;
    int g = lane >> 2, tc = (lane & 3)*2;
    int ar = wm*32 + g;
    #pragma unroll
    for (int p = 0; p < 3; ++p) {
        const __nv_bfloat16* Ap = (p == 1) ? Al : Ah;
        const __nv_bfloat16* Bp = (p == 2) ? Bl : Bh;
        #pragma unroll
        for (int kk = 0; kk < 8; ++kk) {
            int k0 = kk*16;
            unsigned a[2][4], b[4][2];
            #pragma unroll
            for (int mf = 0; mf < 2; ++mf) {
                const __nv_bfloat16* base = Ap + (ar + mf*16)*AST + k0 + tc;
                a[mf][0] = *(const unsigned*)(base);
                a[mf][1] = *(const unsigned*)(base + 8*AST);
                a[mf][2] = *(const unsigned*)(base + 8);
                a[mf][3] = *(const unsigned*)(base + 8*AST + 8);
            }
            #pragma unroll
            for (int nf = 0; nf < 4; ++nf) {
                const __nv_bfloat16* base = Bp + (wn*32 + nf*8 + g)*BST + k0 + tc;
                b[nf][0] = *(const unsigned*)(base);
                b[nf][1] = *(const unsigned*)(base + 8);
            }
            #pragma unroll
            for (int mf = 0; mf < 2; ++mf)
                #pragma unroll
                for (int nf = 0; nf < 4; ++nf)
                    mma16816(acc[mf][nf], a[mf], b[nf]);
        }
    }
}

__device__ __forceinline__ float silu_f(float v) { return v / (1.f + expf(-v)); }

// shared LN row-stats: Vs[64][VST] -> mu_s, rs_s (one warp per row, 8 rows/warp)
__device__ __forceinline__ void ln_stats(const float* Vs, float* mu_s, float* rs_s, int tid) {
    int w = tid >> 5, lane = tid & 31;
    for (int r = w; r < 64; r += 8) {
        float s = 0.f, q = 0.f;
        #pragma unroll
        for (int c = lane; c < 128; c += 32) { float v = Vs[r*VST + c]; s += v; q += v*v; }
        #pragma unroll
        for (int o = 16; o > 0; o >>= 1) {
            s += __shfl_down_sync(0xffffffffu, s, o);
            q += __shfl_down_sync(0xffffffffu, q, o);
        }
        if (lane == 0) {
            float mu = s * (1.f/128.f);
            float var = q * (1.f/128.f) - mu*mu;
            mu_s[r] = mu;
            rs_s[r] = rsqrtf(var + 1e-5f);
        }
    }
}

// G1: h = silu(x@sageW + S1@aggW + sageB) + LN(Xacc@valW * w)
__global__ __launch_bounds__(256, 2) void k_g1(const float* __restrict__ x,
                                               const float* __restrict__ sageW,
                                               const float* __restrict__ sageB,
                                               const float* __restrict__ aggW,
                                               const float* __restrict__ valW,
                                               const float* __restrict__ lnG,
                                               const float* __restrict__ lnB) {
    extern __shared__ __align__(16) char dsm[];
    __nv_bfloat16* Ah = (__nv_bfloat16*)dsm;
    __nv_bfloat16* Al = Ah + 64*AST;
    __nv_bfloat16* Bh = Al + 64*AST;
    __nv_bfloat16* Bl = Bh + 128*BST;
    float* Vs = (float*)dsm;                 // reuse Ah+Al region after GEMMs
    __shared__ float w_s[64], mu_s[64], rs_s[64];
    int tid = threadIdx.x;
    size_t m0 = (size_t)blockIdx.x * 64;
    if (tid < 64) w_s[tid] = g_w[m0 + tid];

    float acc1[2][4][4] = {};
    float acc2[2][4][4] = {};

    mma_stage(x,    sageW, m0, tid, Ah, Al, Bh, Bl, acc1);
    mma_stage(g_S1, aggW,  m0, tid, Ah, Al, Bh, Bl, acc1);
    mma_stage(g_X,  valW,  m0, tid, Ah, Al, Bh, Bl, acc2);

    __syncthreads();   // done with A/B smem; Vs overwrites it
    int lane = tid & 31, w = tid >> 5;
    int wm = w >> 2, wn = w & 3;
    int g = lane >> 2, tc = (lane & 3)*2;

    // stage acc2*w for row LN stats
    #pragma unroll
    for (int mf = 0; mf < 2; ++mf) {
        int r0 = wm*32 + mf*16 + g, r1 = r0 + 8;
        float w0 = w_s[r0], w1 = w_s[r1];
        #pragma unroll
        for (int nf = 0; nf < 4; ++nf) {
            int c = wn*32 + nf*8 + tc;
            *(float2*)&Vs[r0*VST + c] = make_float2(acc2[mf][nf][0]*w0, acc2[mf][nf][1]*w0);
            *(float2*)&Vs[r1*VST + c] = make_float2(acc2[mf][nf][2]*w1, acc2[mf][nf][3]*w1);
        }
    }
    __syncthreads();
    ln_stats(Vs, mu_s, rs_s, tid);
    __syncthreads();

    #pragma unroll
    for (int mf = 0; mf < 2; ++mf) {
        int r0 = wm*32 + mf*16 + g, r1 = r0 + 8;
        float w0 = w_s[r0], w1 = w_s[r1];
        float mu0 = mu_s[r0], rs0 = rs_s[r0];
        float mu1 = mu_s[r1], rs1 = rs_s[r1];
        #pragma unroll
        for (int nf = 0; nf < 4; ++nf) {
            int c = wn*32 + nf*8 + tc;
            float2 sb = *(const float2*)&sageB[c];
            float2 gg = *(const float2*)&lnG[c];
            float2 b2 = *(const float2*)&lnB[c];
            float s00 = silu_f(acc1[mf][nf][0] + sb.x);
            float s01 = silu_f(acc1[mf][nf][1] + sb.y);
            float s10 = silu_f(acc1[mf][nf][2] + sb.x);
            float s11 = silu_f(acc1[mf][nf][3] + sb.y);
            float v00 = acc2[mf][nf][0]*w0, v01 = acc2[mf][nf][1]*w0;
            float v10 = acc2[mf][nf][2]*w1, v11 = acc2[mf][nf][3]*w1;
            float o00 = s00 + (v00 - mu0)*rs0*gg.x + b2.x;
            float o01 = s01 + (v01 - mu0)*rs0*gg.y + b2.y;
            float o10 = s10 + (v10 - mu1)*rs1*gg.x + b2.x;
            float o11 = s11 + (v11 - mu1)*rs1*gg.y + b2.y;
            *(float2*)&g_h[(m0 + r0)*(size_t)D + c] = make_float2(o00, o01);
            *(float2*)&g_h[(m0 + r1)*(size_t)D + c] = make_float2(o10, o11);
        }
    }
}

// G2: out = LN(silu(h@linW + linB))
__global__ __launch_bounds__(256, 2) void k_g2(const float* __restrict__ linW,
                                               const float* __restrict__ linB,
                                               const float* __restrict__ lnG,
                                               const float* __restrict__ lnB,
                                               float* __restrict__ out) {
    extern __shared__ __align__(16) char dsm[];
    __nv_bfloat16* Ah = (__nv_bfloat16*)dsm;
    __nv_bfloat16* Al = Ah + 64*AST;
    __nv_bfloat16* Bh = Al + 64*AST;
    __nv_bfloat16* Bl = Bh + 128*BST;
    float* Vs = (float*)dsm;
    __shared__ float mu_s[64], rs_s[64];
    int tid = threadIdx.x;
    size_t m0 = (size_t)blockIdx.x * 64;

    float acc[2][4][4] = {};
    mma_stage(g_h, linW, m0, tid, Ah, Al, Bh, Bl, acc);

    __syncthreads();
    int lane = tid & 31, w = tid >> 5;
    int wm = w >> 2, wn = w & 3;
    int g = lane >> 2, tc = (lane & 3)*2;

    // y = silu(acc + bias) in-place, stage for stats
    #pragma unroll
    for (int mf = 0; mf < 2; ++mf) {
        int r0 = wm*32 + mf*16 + g, r1 = r0 + 8;
        #pragma unroll
        for (int nf = 0; nf < 4; ++nf) {
            int c = wn*32 + nf*8 + tc;
            float2 bb = *(const float2*)&linB[c];
            acc[mf][nf][0] = silu_f(acc[mf][nf][0] + bb.x);
            acc[mf][nf][1] = silu_f(acc[mf][nf][1] + bb.y);
            acc[mf][nf][2] = silu_f(acc[mf][nf][2] + bb.x);
            acc[mf][nf][3] = silu_f(acc[mf][nf][3] + bb.y);
            *(float2*)&Vs[r0*VST + c] = make_float2(acc[mf][nf][0], acc[mf][nf][1]);
            *(float2*)&Vs[r1*VST + c] = make_float2(acc[mf][nf][2], acc[mf][nf][3]);
        }
    }
    __syncthreads();
    ln_stats(Vs, mu_s, rs_s, tid);
    __syncthreads();

    #pragma unroll
    for (int mf = 0; mf < 2; ++mf) {
        int r0 = wm*32 + mf*16 + g, r1 = r0 + 8;
        float mu0 = mu_s[r0], rs0 = rs_s[r0];
        float mu1 = mu_s[r1], rs1 = rs_s[r1];
        #pragma unroll
        for (int nf = 0; nf < 4; ++nf) {
            int c = wn*32 + nf*8 + tc;
            float2 gg = *(const float2*)&lnG[c];
            float2 b2 = *(const float2*)&lnB[c];
            float o00 = (acc[mf][nf][0] - mu0)*rs0*gg.x + b2.x;
            float o01 = (acc[mf][nf][1] - mu0)*rs0*gg.y + b2.y;
            float o10 = (acc[mf][nf][2] - mu1)*rs1*gg.x + b2.x;
            float o11 = (acc[mf][nf][3] - mu1)*rs1*gg.y + b2.y;
            *(float2*)&out[(m0 + r0)*(size_t)D + c] = make_float2(o00, o01);
            *(float2*)&out[(m0 + r1)*(size_t)D + c] = make_float2(o10, o11);
        }
    }
}

// ---------------- launch ----------------
extern "C" void kernel_launch(void* const* d_in, const int* in_sizes, int n_in,
                              void* d_out, int out_size) {
    const float* x         = (const float*)d_in[0];
    const int*   edge_rows = (const int*)  d_in[1];
    const int*   edge_cols = (const int*)  d_in[2];
    const float* edge_vals = (const float*)d_in[3];
    const float* sage_W    = (const float*)d_in[4];
    const float* sage_b    = (const float*)d_in[5];
    const float* sage_aggW = (const float*)d_in[6];
    const float* key_W     = (const float*)d_in[7];
    const float* query_W   = (const float*)d_in[8];
    const float* value_W   = (const float*)d_in[9];
    const float* attn_ln_g = (const float*)d_in[10];
    const float* attn_ln_b = (const float*)d_in[11];
    const float* lin_W     = (const float*)d_in[12];
    const float* lin_b     = (const float*)d_in[13];
    const float* ln_g      = (const float*)d_in[14];
    const float* ln_b      = (const float*)d_in[15];
    float* out = (float*)d_out;

    // allow >48KB dynamic smem (attribute set; not an allocation)
    cudaFuncSetAttribute(k_g1, cudaFuncAttributeMaxDynamicSharedMemorySize, SMEM_GEMM);
    cudaFuncSetAttribute(k_g2, cudaFuncAttributeMaxDynamicSharedMemorySize, SMEM_GEMM);

    // CSR build
    k_zero_counts<<<(NN + 255)/256, 256>>>();
    k_hist<<<(NE + 255)/256, 256>>>(edge_rows);
    k_scan<<<1, 1024>>>();
    k_scatter<<<(NE + 255)/256, 256>>>(edge_rows, edge_cols, edge_vals);

    // S1 = spmm(x); S2 = spmm(S1) + Xacc epilogue
    k_spmm<<<NN, 128>>>(x, 0);
    k_spmm<<<NN, 128>>>(x, 1);

    // retention weights
    k_weights<<<MROWS/128, 256>>>(x, key_W, query_W);

    // fused sage + value/attn  ->  h   (tensor cores, bf16-split)
    k_g1<<<MROWS/64, 256, SMEM_GEMM>>>(x, sage_W, sage_b, sage_aggW, value_W, attn_ln_g, attn_ln_b);

    // final lin + silu + LN -> out    (tensor cores, bf16-split)
    k_g2<<<MROWS/64, 256, SMEM_GEMM>>>(lin_W, lin_b, ln_g, ln_b, out);
}

// round 6
// speedup vs baseline: 1.5722x; 1.5722x over previous
#include <cuda_runtime.h>
#include <cuda_bf16.h>
#include <math.h>
#include <stdint.h>

#define L 4
#define NN 40000
#define D 128
#define KD 16
#define NE 320000
#define MROWS (L*NN)                 // 160000
#define SLICE ((size_t)NN*(size_t)D) // 5,120,000
#define VST 132                      // LN staging row stride (floats)
#define AST 136                      // A smem row stride (bf16 elems)
#define BST 136                      // B smem/global row stride (bf16 elems, n-major)
#define WSZ (128*BST)                // one converted weight matrix (bf16 elems)

// dynamic smem: Ah(64*AST) Al(64*AST) Bh(128*BST) Bl(128*BST) bf16
#define SMEM_GEMM ((64*AST*2 + 128*BST*2) * 2)   // 104448 bytes

typedef unsigned long long ull;

// ---------------- packed fp32x2 helpers (used by k_weights) ----------------
__device__ __forceinline__ ull pack2(float lo, float hi) {
    ull r; asm("mov.b64 %0, {%1,%2};" : "=l"(r) : "f"(lo), "f"(hi)); return r;
}
__device__ __forceinline__ void fma2(ull& d, ull a, ull b) {
    asm("fma.rn.f32x2 %0, %1, %2, %0;" : "+l"(d) : "l"(a), "l"(b));
}
__device__ __forceinline__ float2 unp2(ull v) {
    float2 r; asm("mov.b64 {%0,%1}, %2;" : "=f"(r.x), "=f"(r.y) : "l"(v)); return r;
}

__device__ __forceinline__ unsigned pkbf(__nv_bfloat16 a, __nv_bfloat16 b) {
    __nv_bfloat162 t = __halves2bfloat162(a, b);
    return *(unsigned*)&t;
}

// ---------------- warp mma m16n8k16 bf16 ----------------
__device__ __forceinline__ void mma16816(float c[4], const unsigned a[4], const unsigned b[2]) {
    asm volatile("mma.sync.aligned.m16n8k16.row.col.f32.bf16.bf16.f32 "
        "{%0,%1,%2,%3},{%4,%5,%6,%7},{%8,%9},{%0,%1,%2,%3};"
        : "+f"(c[0]), "+f"(c[1]), "+f"(c[2]), "+f"(c[3])
        : "r"(a[0]), "r"(a[1]), "r"(a[2]), "r"(a[3]), "r"(b[0]), "r"(b[1]));
}

// ---------------- scratch (static device memory; no allocations) ----------------
static __device__ float g_S1[(size_t)L*NN*D];   // spmm(vals, x)          [L,N,D]
static __device__ float g_S2[(size_t)L*NN*D];   // spmm(vals, S1)         [L,N,D]
static __device__ float g_X [(size_t)L*NN*D];   // x + 0.5 S1 + 0.25 S2   [L,N,D]
static __device__ float g_h [(size_t)L*NN*D];   // sage_out+attn_out      [L,N,D]
static __device__ float g_w [MROWS];            // retention weights      [L*N]
static __device__ int   g_rowptr[NN+1];
static __device__ int   g_cnt[NN];
static __device__ int   g_cur[NN];
static __device__ int   g_ecol[NE];
static __device__ float g_eval[NE];
// precomputed bf16 hi/lo weights, n-major [n*BST + k]; idx: 0=sage 1=agg 2=val 3=lin
static __device__ __align__(16) __nv_bfloat16 g_Wh[4*WSZ];
static __device__ __align__(16) __nv_bfloat16 g_Wl[4*WSZ];

// ---------------- weight precompute: fp32 [k][n] -> bf16 hi/lo [n][k] ----------------
__global__ __launch_bounds__(256) void k_prepw(const float* __restrict__ w0,
                                               const float* __restrict__ w1,
                                               const float* __restrict__ w2,
                                               const float* __restrict__ w3) {
    int idx = blockIdx.x*blockDim.x + threadIdx.x;   // 0 .. 4*16384-1
    if (idx >= 4*128*128) return;
    int m = idx >> 14;
    int r = idx & 16383;
    int k = r >> 7;
    int n = r & 127;
    const float* W = (m == 0) ? w0 : (m == 1) ? w1 : (m == 2) ? w2 : w3;
    float v = W[k*D + n];
    __nv_bfloat16 h = __float2bfloat16(v);
    __nv_bfloat16 l = __float2bfloat16(v - __bfloat162float(h));
    g_Wh[m*WSZ + n*BST + k] = h;
    g_Wl[m*WSZ + n*BST + k] = l;
}

// ---------------- CSR build ----------------
__global__ void k_zero_counts() {
    int i = blockIdx.x*blockDim.x + threadIdx.x;
    if (i < NN) { g_cnt[i] = 0; g_cur[i] = 0; }
}

__global__ void k_hist(const int* __restrict__ rows) {
    int e = blockIdx.x*blockDim.x + threadIdx.x;
    if (e < NE) atomicAdd(&g_cnt[rows[e]], 1);
}

__global__ void k_scan() {
    __shared__ int sh[1024];
    int tid = threadIdx.x;
    int run = 0;
    const int TILES = (NN + 1023) / 1024;
    for (int t = 0; t < TILES; ++t) {
        int i = t*1024 + tid;
        int v = (i < NN) ? g_cnt[i] : 0;
        sh[tid] = v;
        __syncthreads();
        for (int off = 1; off < 1024; off <<= 1) {
            int add = (tid >= off) ? sh[tid - off] : 0;
            __syncthreads();
            sh[tid] += add;
            __syncthreads();
        }
        if (i < NN) g_rowptr[i] = run + sh[tid] - v;   // exclusive
        run += sh[1023];
        __syncthreads();
    }
    if (tid == 0) g_rowptr[NN] = run;
}

__global__ void k_scatter(const int* __restrict__ rows, const int* __restrict__ cols,
                          const float* __restrict__ vals) {
    int e = blockIdx.x*blockDim.x + threadIdx.x;
    if (e < NE) {
        int r = rows[e];
        int p = atomicAdd(&g_cur[r], 1);
        int idx = g_rowptr[r] + p;
        g_ecol[idx] = cols[e];
        g_eval[idx] = vals[e];
    }
}

// ---------------- SPMM ----------------
__global__ __launch_bounds__(128) void k_spmm(const float* __restrict__ x, int stage) {
    const float* __restrict__ in  = (stage == 0) ? x    : (const float*)g_S1;
    float*       __restrict__ out = (stage == 0) ? g_S1 : g_S2;
    int r = blockIdx.x;
    int d = threadIdx.x;
    int s  = g_rowptr[r];
    int e2 = g_rowptr[r+1];
    float a0 = 0.f, a1 = 0.f, a2 = 0.f, a3 = 0.f;
    for (int i = s; i < e2; ++i) {
        int   c = g_ecol[i];
        float v = g_eval[i];
        const float* p = in + (size_t)c*D + d;
        a0 += v * p[0];
        a1 += v * p[SLICE];
        a2 += v * p[2*SLICE];
        a3 += v * p[3*SLICE];
    }
    size_t o = (size_t)r*D + d;
    out[o]           = a0;
    out[o +   SLICE] = a1;
    out[o + 2*SLICE] = a2;
    out[o + 3*SLICE] = a3;
    if (stage == 1) {
        g_X[o]           = x[o]           + 0.5f*in[o]           + 0.25f*a0;
        g_X[o+  SLICE]   = x[o+  SLICE]   + 0.5f*in[o+  SLICE]   + 0.25f*a1;
        g_X[o+2*SLICE]   = x[o+2*SLICE]   + 0.5f*in[o+2*SLICE]   + 0.25f*a2;
        g_X[o+3*SLICE]   = x[o+3*SLICE]   + 0.5f*in[o+3*SLICE]   + 0.25f*a3;
    }
}

// ---------------- retention weights (scalar, proven) ----------------
__global__ __launch_bounds__(256) void k_weights(const float* __restrict__ x,
                                                 const float* __restrict__ keyW,
                                                 const float* __restrict__ qryW) {
    __shared__ __align__(16) float Kw[D*KD];
    __shared__ __align__(16) float Qw[D*KD];
    __shared__ float Zs[32*129];
    __shared__ float wsum[256];
    int tid  = threadIdx.x;
    for (int i = tid; i < D*KD; i += 256) { Kw[i] = keyW[i]; Qw[i] = qryW[i]; }
    int row  = tid & 127;
    int half = tid >> 7;
    size_t m0 = (size_t)blockIdx.x * 128;
    int kb = half * 8;
    float wacc = 0.f;
    #pragma unroll
    for (int t = 0; t < 3; ++t) {
        const float* src = (t == 0) ? x : (t == 1) ? (const float*)g_S1 : (const float*)g_S2;
        float sc = (t == 0) ? 1.f : (t == 1) ? 0.5f : 0.25f;
        ull aK[4] = {0,0,0,0};
        ull aQ[4] = {0,0,0,0};
        for (int dc = 0; dc < D; dc += 32) {
            __syncthreads();
            for (int i = tid; i < 128*32; i += 256) {
                int dd = i & 31, rr = i >> 5;
                Zs[dd*129 + rr] = sc * src[(m0 + rr)*(size_t)D + dc + dd];
            }
            __syncthreads();
            #pragma unroll
            for (int dd = 0; dd < 32; ++dd) {
                float zv = Zs[dd*129 + row];
                ull zp = pack2(zv, zv);
                const ulonglong2* kp = (const ulonglong2*)&Kw[(dc + dd)*KD + kb];
                const ulonglong2* qp = (const ulonglong2*)&Qw[(dc + dd)*KD + kb];
                ulonglong2 k0 = kp[0], k1 = kp[1];
                ulonglong2 q0 = qp[0], q1 = qp[1];
                fma2(aK[0], zp, k0.x); fma2(aK[1], zp, k0.y);
                fma2(aK[2], zp, k1.x); fma2(aK[3], zp, k1.y);
                fma2(aQ[0], zp, q0.x); fma2(aQ[1], zp, q0.y);
                fma2(aQ[2], zp, q1.x); fma2(aQ[3], zp, q1.y);
            }
        }
        float p = 0.f;
        #pragma unroll
        for (int k = 0; k < 4; ++k) {
            float2 fk = unp2(aK[k]), fq = unp2(aQ[k]);
            p += fk.x*fq.x + fk.y*fq.y;
        }
        wacc += p;
    }
    wsum[tid] = wacc;
    __syncthreads();
    if (half == 0) g_w[m0 + row] = (wacc + wsum[tid + 128]) * (1.f/16.f);
}

// ---------------- bf16-split tensor-core GEMM stage ----------------
// acc += A[m0:m0+64, 0:128] @ W[widx] using precomputed bf16 hi/lo weights.
// Passes: Ah@Bh, Al@Bh, Ah@Bl. 256 threads = 8 warps 2(m) x 4(n); warp tile 32x32.
__device__ __forceinline__ void mma_stage(const float* __restrict__ Agl,
                                          int widx,
                                          size_t m0, int tid,
                                          __nv_bfloat16* Ah, __nv_bfloat16* Al,
                                          __nv_bfloat16* Bh, __nv_bfloat16* Bl,
                                          float acc[2][4][4]) {
    __syncthreads();
    // --- A tile convert: 64x128 fp32 -> Ah/Al bf16 (8B stores) ---
    {
        const float4* A4 = (const float4*)Agl;
        #pragma unroll
        for (int i = tid; i < 64*32; i += 256) {
            int r = i >> 5, c4 = i & 31;
            float4 v = A4[(m0 + r)*32 + c4];
            __nv_bfloat16 h0 = __float2bfloat16(v.x), h1 = __float2bfloat16(v.y);
            __nv_bfloat16 h2 = __float2bfloat16(v.z), h3 = __float2bfloat16(v.w);
            __nv_bfloat16 l0 = __float2bfloat16(v.x - __bfloat162float(h0));
            __nv_bfloat16 l1 = __float2bfloat16(v.y - __bfloat162float(h1));
            __nv_bfloat16 l2 = __float2bfloat16(v.z - __bfloat162float(h2));
            __nv_bfloat16 l3 = __float2bfloat16(v.w - __bfloat162float(h3));
            *(uint2*)&Ah[r*AST + c4*4] = make_uint2(pkbf(h0, h1), pkbf(h2, h3));
            *(uint2*)&Al[r*AST + c4*4] = make_uint2(pkbf(l0, l1), pkbf(l2, l3));
        }
        // --- B tiles: straight float4 copy of precomputed hi/lo (layout matches) ---
        const float4* srcH = (const float4*)(g_Wh + (size_t)widx*WSZ);
        const float4* srcL = (const float4*)(g_Wl + (size_t)widx*WSZ);
        float4* dstH = (float4*)Bh;
        float4* dstL = (float4*)Bl;
        #pragma unroll
        for (int i = tid; i < (128*BST)/8; i += 256) {   // 2176 float4 each
            dstH[i] = srcH[i];
            dstL[i] = srcL[i];
        }
    }
    __syncthreads();
    int lane = tid & 31, w = tid >> 5;
    int wm = w >> 2, wn = w & 3;
    int g = lane >> 2, tc = (lane & 3)*2;
    int ar = wm*32 + g;
    #pragma unroll
    for (int p = 0; p < 3; ++p) {
        const __nv_bfloat16* Ap = (p == 1) ? Al : Ah;
        const __nv_bfloat16* Bp = (p == 2) ? Bl : Bh;
        #pragma unroll
        for (int kk = 0; kk < 8; ++kk) {
            int k0 = kk*16;
            unsigned a[2][4], b[4][2];
            #pragma unroll
            for (int mf = 0; mf < 2; ++mf) {
                const __nv_bfloat16* base = Ap + (ar + mf*16)*AST + k0 + tc;
                a[mf][0] = *(const unsigned*)(base);
                a[mf][1] = *(const unsigned*)(base + 8*AST);
                a[mf][2] = *(const unsigned*)(base + 8);
                a[mf][3] = *(const unsigned*)(base + 8*AST + 8);
            }
            #pragma unroll
            for (int nf = 0; nf < 4; ++nf) {
                const __nv_bfloat16* base = Bp + (wn*32 + nf*8 + g)*BST + k0 + tc;
                b[nf][0] = *(const unsigned*)(base);
                b[nf][1] = *(const unsigned*)(base + 8);
            }
            #pragma unroll
            for (int mf = 0; mf < 2; ++mf)
                #pragma unroll
                for (int nf = 0; nf < 4; ++nf)
                    mma16816(acc[mf][nf], a[mf], b[nf]);
        }
    }
}

__device__ __forceinline__ float silu_f(float v) { return v / (1.f + expf(-v)); }

// shared LN row-stats: Vs[64][VST] -> mu_s, rs_s
__device__ __forceinline__ void ln_stats(const float* Vs, float* mu_s, float* rs_s, int tid) {
    int w = tid >> 5, lane = tid & 31;
    for (int r = w; r < 64; r += 8) {
        float s = 0.f, q = 0.f;
        #pragma unroll
        for (int c = lane; c < 128; c += 32) { float v = Vs[r*VST + c]; s += v; q += v*v; }
        #pragma unroll
        for (int o = 16; o > 0; o >>= 1) {
            s += __shfl_down_sync(0xffffffffu, s, o);
            q += __shfl_down_sync(0xffffffffu, q, o);
        }
        if (lane == 0) {
            float mu = s * (1.f/128.f);
            float var = q * (1.f/128.f) - mu*mu;
            mu_s[r] = mu;
            rs_s[r] = rsqrtf(var + 1e-5f);
        }
    }
}

// G1: h = silu(x@sageW + S1@aggW + sageB) + LN(Xacc@valW * w)
__global__ __launch_bounds__(256, 2) void k_g1(const float* __restrict__ x,
                                               const float* __restrict__ sageB,
                                               const float* __restrict__ lnG,
                                               const float* __restrict__ lnB) {
    extern __shared__ __align__(16) char dsm[];
    __nv_bfloat16* Ah = (__nv_bfloat16*)dsm;
    __nv_bfloat16* Al = Ah + 64*AST;
    __nv_bfloat16* Bh = Al + 64*AST;
    __nv_bfloat16* Bl = Bh + 128*BST;
    float* Vs = (float*)dsm;                 // reuse A region after GEMMs
    __shared__ float w_s[64], mu_s[64], rs_s[64];
    int tid = threadIdx.x;
    size_t m0 = (size_t)blockIdx.x * 64;
    if (tid < 64) w_s[tid] = g_w[m0 + tid];

    float acc1[2][4][4] = {};
    float acc2[2][4][4] = {};

    mma_stage(x,    0, m0, tid, Ah, Al, Bh, Bl, acc1);   // sageW
    mma_stage(g_S1, 1, m0, tid, Ah, Al, Bh, Bl, acc1);   // aggW
    mma_stage(g_X,  2, m0, tid, Ah, Al, Bh, Bl, acc2);   // valW

    __syncthreads();
    int lane = tid & 31, w = tid >> 5;
    int wm = w >> 2, wn = w & 3;
    int g = lane >> 2, tc = (lane & 3)*2;

    #pragma unroll
    for (int mf = 0; mf < 2; ++mf) {
        int r0 = wm*32 + mf*16 + g, r1 = r0 + 8;
        float w0 = w_s[r0], w1 = w_s[r1];
        #pragma unroll
        for (int nf = 0; nf < 4; ++nf) {
            int c = wn*32 + nf*8 + tc;
            *(float2*)&Vs[r0*VST + c] = make_float2(acc2[mf][nf][0]*w0, acc2[mf][nf][1]*w0);
            *(float2*)&Vs[r1*VST + c] = make_float2(acc2[mf][nf][2]*w1, acc2[mf][nf][3]*w1);
        }
    }
    __syncthreads();
    ln_stats(Vs, mu_s, rs_s, tid);
    __syncthreads();

    #pragma unroll
    for (int mf = 0; mf < 2; ++mf) {
        int r0 = wm*32 + mf*16 + g, r1 = r0 + 8;
        float w0 = w_s[r0], w1 = w_s[r1];
        float mu0 = mu_s[r0], rs0 = rs_s[r0];
        float mu1 = mu_s[r1], rs1 = rs_s[r1];
        #pragma unroll
        for (int nf = 0; nf < 4; ++nf) {
            int c = wn*32 + nf*8 + tc;
            float2 sb = *(const float2*)&sageB[c];
            float2 gg = *(const float2*)&lnG[c];
            float2 b2 = *(const float2*)&lnB[c];
            float s00 = silu_f(acc1[mf][nf][0] + sb.x);
            float s01 = silu_f(acc1[mf][nf][1] + sb.y);
            float s10 = silu_f(acc1[mf][nf][2] + sb.x);
            float s11 = silu_f(acc1[mf][nf][3] + sb.y);
            float v00 = acc2[mf][nf][0]*w0, v01 = acc2[mf][nf][1]*w0;
            float v10 = acc2[mf][nf][2]*w1, v11 = acc2[mf][nf][3]*w1;
            float o00 = s00 + (v00 - mu0)*rs0*gg.x + b2.x;
            float o01 = s01 + (v01 - mu0)*rs0*gg.y + b2.y;
            float o10 = s10 + (v10 - mu1)*rs1*gg.x + b2.x;
            float o11 = s11 + (v11 - mu1)*rs1*gg.y + b2.y;
            *(float2*)&g_h[(m0 + r0)*(size_t)D + c] = make_float2(o00, o01);
            *(float2*)&g_h[(m0 + r1)*(size_t)D + c] = make_float2(o10, o11);
        }
    }
}

// G2: out = LN(silu(h@linW + linB))
__global__ __launch_bounds__(256, 2) void k_g2(const float* __restrict__ linB,
                                               const float* __restrict__ lnG,
                                               const float* __restrict__ lnB,
                                               float* __restrict__ out) {
    extern __shared__ __align__(16) char dsm[];
    __nv_bfloat16* Ah = (__nv_bfloat16*)dsm;
    __nv_bfloat16* Al = Ah + 64*AST;
    __nv_bfloat16* Bh = Al + 64*AST;
    __nv_bfloat16* Bl = Bh + 128*BST;
    float* Vs = (float*)dsm;
    __shared__ float mu_s[64], rs_s[64];
    int tid = threadIdx.x;
    size_t m0 = (size_t)blockIdx.x * 64;

    float acc[2][4][4] = {};
    mma_stage(g_h, 3, m0, tid, Ah, Al, Bh, Bl, acc);     // linW

    __syncthreads();
    int lane = tid & 31, w = tid >> 5;
    int wm = w >> 2, wn = w & 3;
    int g = lane >> 2, tc = (lane & 3)*2;

    #pragma unroll
    for (int mf = 0; mf < 2; ++mf) {
        int r0 = wm*32 + mf*16 + g, r1 = r0 + 8;
        #pragma unroll
        for (int nf = 0; nf < 4; ++nf) {
            int c = wn*32 + nf*8 + tc;
            float2 bb = *(const float2*)&linB[c];
            acc[mf][nf][0] = silu_f(acc[mf][nf][0] + bb.x);
            acc[mf][nf][1] = silu_f(acc[mf][nf][1] + bb.y);
            acc[mf][nf][2] = silu_f(acc[mf][nf][2] + bb.x);
            acc[mf][nf][3] = silu_f(acc[mf][nf][3] + bb.y);
            *(float2*)&Vs[r0*VST + c] = make_float2(acc[mf][nf][0], acc[mf][nf][1]);
            *(float2*)&Vs[r1*VST + c] = make_float2(acc[mf][nf][2], acc[mf][nf][3]);
        }
    }
    __syncthreads();
    ln_stats(Vs, mu_s, rs_s, tid);
    __syncthreads();

    #pragma unroll
    for (int mf = 0; mf < 2; ++mf) {
        int r0 = wm*32 + mf*16 + g, r1 = r0 + 8;
        float mu0 = mu_s[r0], rs0 = rs_s[r0];
        float mu1 = mu_s[r1], rs1 = rs_s[r1];
        #pragma unroll
        for (int nf = 0; nf < 4; ++nf) {
            int c = wn*32 + nf*8 + tc;
            float2 gg = *(const float2*)&lnG[c];
            float2 b2 = *(const float2*)&lnB[c];
            float o00 = (acc[mf][nf][0] - mu0)*rs0*gg.x + b2.x;
            float o01 = (acc[mf][nf][1] - mu0)*rs0*gg.y + b2.y;
            float o10 = (acc[mf][nf][2] - mu1)*rs1*gg.x + b2.x;
            float o11 = (acc[mf][nf][3] - mu1)*rs1*gg.y + b2.y;
            *(float2*)&out[(m0 + r0)*(size_t)D + c] = make_float2(o00, o01);
            *(float2*)&out[(m0 + r1)*(size_t)D + c] = make_float2(o10, o11);
        }
    }
}

// ---------------- launch ----------------
extern "C" void kernel_launch(void* const* d_in, const int* in_sizes, int n_in,
                              void* d_out, int out_size) {
    const float* x         = (const float*)d_in[0];
    const int*   edge_rows = (const int*)  d_in[1];
    const int*   edge_cols = (const int*)  d_in[2];
    const float* edge_vals = (const float*)d_in[3];
    const float* sage_W    = (const float*)d_in[4];
    const float* sage_b    = (const float*)d_in[5];
    const float* sage_aggW = (const float*)d_in[6];
    const float* key_W     = (const float*)d_in[7];
    const float* query_W   = (const float*)d_in[8];
    const float* value_W   = (const float*)d_in[9];
    const float* attn_ln_g = (const float*)d_in[10];
    const float* attn_ln_b = (const float*)d_in[11];
    const float* lin_W     = (const float*)d_in[12];
    const float* lin_b     = (const float*)d_in[13];
    const float* ln_g      = (const float*)d_in[14];
    const float* ln_b      = (const float*)d_in[15];
    float* out = (float*)d_out;

    cudaFuncSetAttribute(k_g1, cudaFuncAttributeMaxDynamicSharedMemorySize, SMEM_GEMM);
    cudaFuncSetAttribute(k_g2, cudaFuncAttributeMaxDynamicSharedMemorySize, SMEM_GEMM);

    // weight precompute (bf16 hi/lo, n-major)
    k_prepw<<<(4*128*128 + 255)/256, 256>>>(sage_W, sage_aggW, value_W, lin_W);

    // CSR build
    k_zero_counts<<<(NN + 255)/256, 256>>>();
    k_hist<<<(NE + 255)/256, 256>>>(edge_rows);
    k_scan<<<1, 1024>>>();
    k_scatter<<<(NE + 255)/256, 256>>>(edge_rows, edge_cols, edge_vals);

    // S1 = spmm(x); S2 = spmm(S1) + Xacc epilogue
    k_spmm<<<NN, 128>>>(x, 0);
    k_spmm<<<NN, 128>>>(x, 1);

    // retention weights
    k_weights<<<MROWS/128, 256>>>(x, key_W, query_W);

    // fused sage + value/attn  ->  h   (tensor cores, precomputed bf16 weights)
    k_g1<<<MROWS/64, 256, SMEM_GEMM>>>(x, sage_b, attn_ln_g, attn_ln_b);

    // final lin + silu + LN -> out
    k_g2<<<MROWS/64, 256, SMEM_GEMM>>>(lin_b, ln_g, ln_b, out);
}

// round 7
// speedup vs baseline: 1.7151x; 1.0909x over previous
#include <cuda_runtime.h>
#include <cuda_bf16.h>
#include <math.h>
#include <stdint.h>

#define L 4
#define NN 40000
#define D 128
#define KD 16
#define NE 320000
#define MROWS (L*NN)                 // 160000
#define SLICE ((size_t)NN*(size_t)D) // 5,120,000
#define VST 132                      // LN staging row stride (floats)
#define AST 136                      // A smem row stride (bf16 elems)
#define BST 136                      // B smem/global row stride (bf16 elems, n-major)
#define WSZ (128*BST)                // one converted weight matrix (bf16 elems)
#define WST 33                       // Ws staging row stride (floats)

// dynamic smem: Ah(64*AST) Al(64*AST) Bh(128*BST) Bl(128*BST) bf16
#define SMEM_GEMM ((64*AST*2 + 128*BST*2) * 2)   // 104448 bytes

__device__ __forceinline__ unsigned pkbf(__nv_bfloat16 a, __nv_bfloat16 b) {
    __nv_bfloat162 t = __halves2bfloat162(a, b);
    return *(unsigned*)&t;
}

// ---------------- warp mma m16n8k16 bf16 ----------------
__device__ __forceinline__ void mma16816(float c[4], const unsigned a[4], const unsigned b[2]) {
    asm volatile("mma.sync.aligned.m16n8k16.row.col.f32.bf16.bf16.f32 "
        "{%0,%1,%2,%3},{%4,%5,%6,%7},{%8,%9},{%0,%1,%2,%3};"
        : "+f"(c[0]), "+f"(c[1]), "+f"(c[2]), "+f"(c[3])
        : "r"(a[0]), "r"(a[1]), "r"(a[2]), "r"(a[3]), "r"(b[0]), "r"(b[1]));
}

// ---------------- scratch (static device memory; no allocations) ----------------
static __device__ float g_S1[(size_t)L*NN*D];   // spmm(vals, x)          [L,N,D]
static __device__ float g_X [(size_t)L*NN*D];   // x + 0.5 S1 + 0.25 S2   [L,N,D]
static __device__ float g_h [(size_t)L*NN*D];   // sage_out+attn_out      [L,N,D]
static __device__ int   g_rowptr[NN+1];
static __device__ int   g_cnt[NN];
static __device__ int   g_cur[NN];
static __device__ int   g_ecol[NE];
static __device__ float g_eval[NE];
// precomputed bf16 hi/lo weights, n-major [n*BST + k]; idx: 0=sage 1=agg 2=val 3=lin
static __device__ __align__(16) __nv_bfloat16 g_Wh[4*WSZ];
static __device__ __align__(16) __nv_bfloat16 g_Wl[4*WSZ];
// KQ = [Kw | Qw] bf16 hi/lo, n-major [n*128 + k], n: 0-15 key cols, 16-31 query cols
static __device__ __align__(16) __nv_bfloat16 g_KQh[32*128];
static __device__ __align__(16) __nv_bfloat16 g_KQl[32*128];

// ---------------- weight precompute ----------------
__global__ __launch_bounds__(256) void k_prepw(const float* __restrict__ w0,
                                               const float* __restrict__ w1,
                                               const float* __restrict__ w2,
                                               const float* __restrict__ w3,
                                               const float* __restrict__ keyW,
                                               const float* __restrict__ qryW) {
    int idx = blockIdx.x*blockDim.x + threadIdx.x;
    if (idx < 4*128*128) {
        int m = idx >> 14;
        int r = idx & 16383;
        int k = r >> 7;
        int n = r & 127;
        const float* W = (m == 0) ? w0 : (m == 1) ? w1 : (m == 2) ? w2 : w3;
        float v = W[k*D + n];
        __nv_bfloat16 h = __float2bfloat16(v);
        __nv_bfloat16 l = __float2bfloat16(v - __bfloat162float(h));
        g_Wh[m*WSZ + n*BST + k] = h;
        g_Wl[m*WSZ + n*BST + k] = l;
    } else if (idx < 4*128*128 + 32*128) {
        int r = idx - 4*128*128;   // 0..4095
        int n = r >> 7;            // 0..31
        int k = r & 127;
        float v = (n < KD) ? keyW[k*KD + n] : qryW[k*KD + (n - KD)];
        __nv_bfloat16 h = __float2bfloat16(v);
        __nv_bfloat16 l = __float2bfloat16(v - __bfloat162float(h));
        g_KQh[n*128 + k] = h;
        g_KQl[n*128 + k] = l;
    }
}

// ---------------- CSR build ----------------
__global__ void k_zero_counts() {
    int i = blockIdx.x*blockDim.x + threadIdx.x;
    if (i < NN) { g_cnt[i] = 0; g_cur[i] = 0; }
}

__global__ void k_hist(const int* __restrict__ rows) {
    int e = blockIdx.x*blockDim.x + threadIdx.x;
    if (e < NE) atomicAdd(&g_cnt[rows[e]], 1);
}

// chunk-per-thread + warp-shuffle block scan (1024 threads, chunk 40)
__global__ __launch_bounds__(1024) void k_scan() {
    __shared__ int wsum[32];
    __shared__ int s_total;
    int tid = threadIdx.x;
    const int CH = 40;                 // 1024*40 = 40960 >= NN
    int base = tid * CH;
    int local = 0;
    for (int j = 0; j < CH; ++j) {
        int i = base + j;
        if (i < NN) local += g_cnt[i];
    }
    int lane = tid & 31, wid = tid >> 5;
    int v = local;
    #pragma unroll
    for (int o = 1; o < 32; o <<= 1) {
        int t = __shfl_up_sync(0xffffffffu, v, o);
        if (lane >= o) v += t;
    }
    if (lane == 31) wsum[wid] = v;
    __syncthreads();
    if (wid == 0) {
        int s = wsum[lane];
        #pragma unroll
        for (int o = 1; o < 32; o <<= 1) {
            int t = __shfl_up_sync(0xffffffffu, s, o);
            if (lane >= o) s += t;
        }
        wsum[lane] = s;
        if (lane == 31) s_total = s;
    }
    __syncthreads();
    int run = v - local + ((wid > 0) ? wsum[wid-1] : 0);   // exclusive base
    for (int j = 0; j < CH; ++j) {
        int i = base + j;
        if (i < NN) { g_rowptr[i] = run; run += g_cnt[i]; }
    }
    if (tid == 0) g_rowptr[NN] = s_total;
}

__global__ void k_scatter(const int* __restrict__ rows, const int* __restrict__ cols,
                          const float* __restrict__ vals) {
    int e = blockIdx.x*blockDim.x + threadIdx.x;
    if (e < NE) {
        int r = rows[e];
        int p = atomicAdd(&g_cur[r], 1);
        int idx = g_rowptr[r] + p;
        g_ecol[idx] = cols[e];
        g_eval[idx] = vals[e];
    }
}

// ---------------- SPMM ----------------
// stage 0: S1 = spmm(x).  stage 1: compute S2 = spmm(S1) locally, write only g_X.
__global__ __launch_bounds__(128) void k_spmm(const float* __restrict__ x, int stage) {
    const float* __restrict__ in = (stage == 0) ? x : (const float*)g_S1;
    int r = blockIdx.x;
    int d = threadIdx.x;
    int s  = g_rowptr[r];
    int e2 = g_rowptr[r+1];
    float a0 = 0.f, a1 = 0.f, a2 = 0.f, a3 = 0.f;
    for (int i = s; i < e2; ++i) {
        int   c = g_ecol[i];
        float v = g_eval[i];
        const float* p = in + (size_t)c*D + d;
        a0 += v * p[0];
        a1 += v * p[SLICE];
        a2 += v * p[2*SLICE];
        a3 += v * p[3*SLICE];
    }
    size_t o = (size_t)r*D + d;
    if (stage == 0) {
        g_S1[o]           = a0;
        g_S1[o +   SLICE] = a1;
        g_S1[o + 2*SLICE] = a2;
        g_S1[o + 3*SLICE] = a3;
    } else {
        g_X[o]           = x[o]           + 0.5f*in[o]           + 0.25f*a0;
        g_X[o+  SLICE]   = x[o+  SLICE]   + 0.5f*in[o+  SLICE]   + 0.25f*a1;
        g_X[o+2*SLICE]   = x[o+2*SLICE]   + 0.5f*in[o+2*SLICE]   + 0.25f*a2;
        g_X[o+3*SLICE]   = x[o+3*SLICE]   + 0.5f*in[o+3*SLICE]   + 0.25f*a3;
    }
}

// ---------------- bf16-split tensor-core GEMM stage ----------------
// acc += A[m0:m0+64, :] @ W[widx]; if WQ also accW += A @ [Kw|Qw] (32 cols).
// Passes: Ah@Bh, Al@Bh, Ah@Bl. 256 threads = 8 warps 2(m) x 4(n); warp tile 32x32.
template<bool WQ>
__device__ __forceinline__ void mma_stage(const float* __restrict__ Agl,
                                          int widx,
                                          size_t m0, int tid,
                                          __nv_bfloat16* Ah, __nv_bfloat16* Al,
                                          __nv_bfloat16* Bh, __nv_bfloat16* Bl,
                                          float acc[2][4][4], float accW[2][4]) {
    __syncthreads();
    {
        const float4* A4 = (const float4*)Agl;
        #pragma unroll
        for (int i = tid; i < 64*32; i += 256) {
            int r = i >> 5, c4 = i & 31;
            float4 v = A4[(m0 + r)*32 + c4];
            __nv_bfloat16 h0 = __float2bfloat16(v.x), h1 = __float2bfloat16(v.y);
            __nv_bfloat16 h2 = __float2bfloat16(v.z), h3 = __float2bfloat16(v.w);
            __nv_bfloat16 l0 = __float2bfloat16(v.x - __bfloat162float(h0));
            __nv_bfloat16 l1 = __float2bfloat16(v.y - __bfloat162float(h1));
            __nv_bfloat16 l2 = __float2bfloat16(v.z - __bfloat162float(h2));
            __nv_bfloat16 l3 = __float2bfloat16(v.w - __bfloat162float(h3));
            *(uint2*)&Ah[r*AST + c4*4] = make_uint2(pkbf(h0, h1), pkbf(h2, h3));
            *(uint2*)&Al[r*AST + c4*4] = make_uint2(pkbf(l0, l1), pkbf(l2, l3));
        }
        const float4* srcH = (const float4*)(g_Wh + (size_t)widx*WSZ);
        const float4* srcL = (const float4*)(g_Wl + (size_t)widx*WSZ);
        float4* dstH = (float4*)Bh;
        float4* dstL = (float4*)Bl;
        #pragma unroll
        for (int i = tid; i < (128*BST)/8; i += 256) {
            dstH[i] = srcH[i];
            dstL[i] = srcL[i];
        }
    }
    __syncthreads();
    int lane = tid & 31, w = tid >> 5;
    int wm = w >> 2, wn = w & 3;
    int g = lane >> 2, tc = (lane & 3)*2;
    int ar = wm*32 + g;
    #pragma unroll
    for (int p = 0; p < 3; ++p) {
        const __nv_bfloat16* Ap = (p == 1) ? Al : Ah;
        const __nv_bfloat16* Bp = (p == 2) ? Bl : Bh;
        const __nv_bfloat16* KQp = (p == 2) ? g_KQl : g_KQh;
        #pragma unroll
        for (int kk = 0; kk < 8; ++kk) {
            int k0 = kk*16;
            unsigned a[2][4], b[4][2];
            #pragma unroll
            for (int mf = 0; mf < 2; ++mf) {
                const __nv_bfloat16* base = Ap + (ar + mf*16)*AST + k0 + tc;
                a[mf][0] = *(const unsigned*)(base);
                a[mf][1] = *(const unsigned*)(base + 8*AST);
                a[mf][2] = *(const unsigned*)(base + 8);
                a[mf][3] = *(const unsigned*)(base + 8*AST + 8);
            }
            #pragma unroll
            for (int nf = 0; nf < 4; ++nf) {
                const __nv_bfloat16* base = Bp + (wn*32 + nf*8 + g)*BST + k0 + tc;
                b[nf][0] = *(const unsigned*)(base);
                b[nf][1] = *(const unsigned*)(base + 8);
            }
            #pragma unroll
            for (int mf = 0; mf < 2; ++mf)
                #pragma unroll
                for (int nf = 0; nf < 4; ++nf)
                    mma16816(acc[mf][nf], a[mf], b[nf]);
            if (WQ) {
                const __nv_bfloat16* kb = KQp + (wn*8 + g)*128 + k0 + tc;
                unsigned kq[2];
                kq[0] = *(const unsigned*)(kb);
                kq[1] = *(const unsigned*)(kb + 8);
                mma16816(accW[0], a[0], kq);
                mma16816(accW[1], a[1], kq);
            }
        }
    }
}

__device__ __forceinline__ float silu_f(float v) { return v / (1.f + expf(-v)); }

// shared LN row-stats: Vs[64][VST] -> mu_s, rs_s
__device__ __forceinline__ void ln_stats(const float* Vs, float* mu_s, float* rs_s, int tid) {
    int w = tid >> 5, lane = tid & 31;
    for (int r = w; r < 64; r += 8) {
        float s = 0.f, q = 0.f;
        #pragma unroll
        for (int c = lane; c < 128; c += 32) { float v = Vs[r*VST + c]; s += v; q += v*v; }
        #pragma unroll
        for (int o = 16; o > 0; o >>= 1) {
            s += __shfl_down_sync(0xffffffffu, s, o);
            q += __shfl_down_sync(0xffffffffu, q, o);
        }
        if (lane == 0) {
            float mu = s * (1.f/128.f);
            float var = q * (1.f/128.f) - mu*mu;
            mu_s[r] = mu;
            rs_s[r] = rsqrtf(var + 1e-5f);
        }
    }
}

// G1: h = silu(x@sageW + S1@aggW + sageB) + LN(Xacc@valW * w), w computed in-kernel
__global__ __launch_bounds__(256, 2) void k_g1(const float* __restrict__ x,
                                               const float* __restrict__ sageB,
                                               const float* __restrict__ lnG,
                                               const float* __restrict__ lnB) {
    extern __shared__ __align__(16) char dsm[];
    __nv_bfloat16* Ah = (__nv_bfloat16*)dsm;
    __nv_bfloat16* Al = Ah + 64*AST;
    __nv_bfloat16* Bh = Al + 64*AST;
    __nv_bfloat16* Bl = Bh + 128*BST;
    float* Ws = (float*)dsm;                 // [3][64][WST] after stages
    float* Vs = (float*)dsm;                 // [64][VST] after w computed
    __shared__ float w_s[64], mu_s[64], rs_s[64];
    int tid = threadIdx.x;
    size_t m0 = (size_t)blockIdx.x * 64;

    float acc1[2][4][4] = {};
    float acc2[2][4][4] = {};
    float aW0[2][4] = {};
    float aW1[2][4] = {};
    float aW2[2][4] = {};

    mma_stage<true>(x,    0, m0, tid, Ah, Al, Bh, Bl, acc1, aW0);   // sageW | x@KQ
    mma_stage<true>(g_S1, 1, m0, tid, Ah, Al, Bh, Bl, acc1, aW1);   // aggW  | S1@KQ
    mma_stage<true>(g_X,  2, m0, tid, Ah, Al, Bh, Bl, acc2, aW2);   // valW  | gX@KQ

    __syncthreads();
    int lane = tid & 31, w = tid >> 5;
    int wm = w >> 2, wn = w & 3;
    int g = lane >> 2, tc = (lane & 3)*2;

    // stage accW fragments to Ws[3][64][WST]
    #pragma unroll
    for (int mf = 0; mf < 2; ++mf) {
        int r0 = wm*32 + mf*16 + g, r1 = r0 + 8;
        int c = wn*8 + tc;
        Ws[(      r0)*WST + c] = aW0[mf][0]; Ws[(      r0)*WST + c + 1] = aW0[mf][1];
        Ws[(      r1)*WST + c] = aW0[mf][2]; Ws[(      r1)*WST + c + 1] = aW0[mf][3];
        Ws[( 64 + r0)*WST + c] = aW1[mf][0]; Ws[( 64 + r0)*WST + c + 1] = aW1[mf][1];
        Ws[( 64 + r1)*WST + c] = aW1[mf][2]; Ws[( 64 + r1)*WST + c + 1] = aW1[mf][3];
        Ws[(128 + r0)*WST + c] = aW2[mf][0]; Ws[(128 + r0)*WST + c + 1] = aW2[mf][1];
        Ws[(128 + r1)*WST + c] = aW2[mf][2]; Ws[(128 + r1)*WST + c + 1] = aW2[mf][3];
    }
    __syncthreads();

    // w per row: z0=x, z1=0.5*S1, z2 = gX - x - 0.5*S1
    {
        int row = tid >> 2, part = tid & 3;
        float a = 0.f;
        #pragma unroll
        for (int j = 0; j < 4; ++j) {
            int k = part*4 + j;
            float pX = Ws[row*WST + k],            qX = Ws[row*WST + 16 + k];
            float pS = 0.5f*Ws[(64 + row)*WST + k], qS = 0.5f*Ws[(64 + row)*WST + 16 + k];
            float pG = Ws[(128 + row)*WST + k],     qG = Ws[(128 + row)*WST + 16 + k];
            float p2 = pG - pX - pS, q2 = qG - qX - qS;
            a += pX*qX + pS*qS + p2*q2;
        }
        a += __shfl_xor_sync(0xffffffffu, a, 1);
        a += __shfl_xor_sync(0xffffffffu, a, 2);
        if (part == 0) w_s[row] = a * (1.f/16.f);
    }
    __syncthreads();

    // stage acc2*w for row LN stats (overwrites Ws — dead now)
    #pragma unroll
    for (int mf = 0; mf < 2; ++mf) {
        int r0 = wm*32 + mf*16 + g, r1 = r0 + 8;
        float w0 = w_s[r0], w1 = w_s[r1];
        #pragma unroll
        for (int nf = 0; nf < 4; ++nf) {
            int c = wn*32 + nf*8 + tc;
            *(float2*)&Vs[r0*VST + c] = make_float2(acc2[mf][nf][0]*w0, acc2[mf][nf][1]*w0);
            *(float2*)&Vs[r1*VST + c] = make_float2(acc2[mf][nf][2]*w1, acc2[mf][nf][3]*w1);
        }
    }
    __syncthreads();
    ln_stats(Vs, mu_s, rs_s, tid);
    __syncthreads();

    #pragma unroll
    for (int mf = 0; mf < 2; ++mf) {
        int r0 = wm*32 + mf*16 + g, r1 = r0 + 8;
        float w0 = w_s[r0], w1 = w_s[r1];
        float mu0 = mu_s[r0], rs0 = rs_s[r0];
        float mu1 = mu_s[r1], rs1 = rs_s[r1];
        #pragma unroll
        for (int nf = 0; nf < 4; ++nf) {
            int c = wn*32 + nf*8 + tc;
            float2 sb = *(const float2*)&sageB[c];
            float2 gg = *(const float2*)&lnG[c];
            float2 b2 = *(const float2*)&lnB[c];
            float s00 = silu_f(acc1[mf][nf][0] + sb.x);
            float s01 = silu_f(acc1[mf][nf][1] + sb.y);
            float s10 = silu_f(acc1[mf][nf][2] + sb.x);
            float s11 = silu_f(acc1[mf][nf][3] + sb.y);
            float v00 = acc2[mf][nf][0]*w0, v01 = acc2[mf][nf][1]*w0;
            float v10 = acc2[mf][nf][2]*w1, v11 = acc2[mf][nf][3]*w1;
            float o00 = s00 + (v00 - mu0)*rs0*gg.x + b2.x;
            float o01 = s01 + (v01 - mu0)*rs0*gg.y + b2.y;
            float o10 = s10 + (v10 - mu1)*rs1*gg.x + b2.x;
            float o11 = s11 + (v11 - mu1)*rs1*gg.y + b2.y;
            *(float2*)&g_h[(m0 + r0)*(size_t)D + c] = make_float2(o00, o01);
            *(float2*)&g_h[(m0 + r1)*(size_t)D + c] = make_float2(o10, o11);
        }
    }
}

// G2: out = LN(silu(h@linW + linB))
__global__ __launch_bounds__(256, 2) void k_g2(const float* __restrict__ linB,
                                               const float* __restrict__ lnG,
                                               const float* __restrict__ lnB,
                                               float* __restrict__ out) {
    extern __shared__ __align__(16) char dsm[];
    __nv_bfloat16* Ah = (__nv_bfloat16*)dsm;
    __nv_bfloat16* Al = Ah + 64*AST;
    __nv_bfloat16* Bh = Al + 64*AST;
    __nv_bfloat16* Bl = Bh + 128*BST;
    float* Vs = (float*)dsm;
    __shared__ float mu_s[64], rs_s[64];
    int tid = threadIdx.x;
    size_t m0 = (size_t)blockIdx.x * 64;

    float acc[2][4][4] = {};
    float aWd[2][4];
    mma_stage<false>(g_h, 3, m0, tid, Ah, Al, Bh, Bl, acc, aWd);   // linW

    __syncthreads();
    int lane = tid & 31, w = tid >> 5;
    int wm = w >> 2, wn = w & 3;
    int g = lane >> 2, tc = (lane & 3)*2;

    #pragma unroll
    for (int mf = 0; mf < 2; ++mf) {
        int r0 = wm*32 + mf*16 + g, r1 = r0 + 8;
        #pragma unroll
        for (int nf = 0; nf < 4; ++nf) {
            int c = wn*32 + nf*8 + tc;
            float2 bb = *(const float2*)&linB[c];
            acc[mf][nf][0] = silu_f(acc[mf][nf][0] + bb.x);
            acc[mf][nf][1] = silu_f(acc[mf][nf][1] + bb.y);
            acc[mf][nf][2] = silu_f(acc[mf][nf][2] + bb.x);
            acc[mf][nf][3] = silu_f(acc[mf][nf][3] + bb.y);
            *(float2*)&Vs[r0*VST + c] = make_float2(acc[mf][nf][0], acc[mf][nf][1]);
            *(float2*)&Vs[r1*VST + c] = make_float2(acc[mf][nf][2], acc[mf][nf][3]);
        }
    }
    __syncthreads();
    ln_stats(Vs, mu_s, rs_s, tid);
    __syncthreads();

    #pragma unroll
    for (int mf = 0; mf < 2; ++mf) {
        int r0 = wm*32 + mf*16 + g, r1 = r0 + 8;
        float mu0 = mu_s[r0], rs0 = rs_s[r0];
        float mu1 = mu_s[r1], rs1 = rs_s[r1];
        #pragma unroll
        for (int nf = 0; nf < 4; ++nf) {
            int c = wn*32 + nf*8 + tc;
            float2 gg = *(const float2*)&lnG[c];
            float2 b2 = *(const float2*)&lnB[c];
            float o00 = (acc[mf][nf][0] - mu0)*rs0*gg.x + b2.x;
            float o01 = (acc[mf][nf][1] - mu0)*rs0*gg.y + b2.y;
            float o10 = (acc[mf][nf][2] - mu1)*rs1*gg.x + b2.x;
            float o11 = (acc[mf][nf][3] - mu1)*rs1*gg.y + b2.y;
            *(float2*)&out[(m0 + r0)*(size_t)D + c] = make_float2(o00, o01);
            *(float2*)&out[(m0 + r1)*(size_t)D + c] = make_float2(o10, o11);
        }
    }
}

// ---------------- launch ----------------
extern "C" void kernel_launch(void* const* d_in, const int* in_sizes, int n_in,
                              void* d_out, int out_size) {
    const float* x         = (const float*)d_in[0];
    const int*   edge_rows = (const int*)  d_in[1];
    const int*   edge_cols = (const int*)  d_in[2];
    const float* edge_vals = (const float*)d_in[3];
    const float* sage_W    = (const float*)d_in[4];
    const float* sage_b    = (const float*)d_in[5];
    const float* sage_aggW = (const float*)d_in[6];
    const float* key_W     = (const float*)d_in[7];
    const float* query_W   = (const float*)d_in[8];
    const float* value_W   = (const float*)d_in[9];
    const float* attn_ln_g = (const float*)d_in[10];
    const float* attn_ln_b = (const float*)d_in[11];
    const float* lin_W     = (const float*)d_in[12];
    const float* lin_b     = (const float*)d_in[13];
    const float* ln_g      = (const float*)d_in[14];
    const float* ln_b      = (const float*)d_in[15];
    float* out = (float*)d_out;

    cudaFuncSetAttribute(k_g1, cudaFuncAttributeMaxDynamicSharedMemorySize, SMEM_GEMM);
    cudaFuncSetAttribute(k_g2, cudaFuncAttributeMaxDynamicSharedMemorySize, SMEM_GEMM);

    // weight + KQ precompute (bf16 hi/lo)
    k_prepw<<<(4*128*128 + 32*128 + 255)/256, 256>>>(sage_W, sage_aggW, value_W, lin_W,
                                                     key_W, query_W);

    // CSR build
    k_zero_counts<<<(NN + 255)/256, 256>>>();
    k_hist<<<(NE + 255)/256, 256>>>(edge_rows);
    k_scan<<<1, 1024>>>();
    k_scatter<<<(NE + 255)/256, 256>>>(edge_rows, edge_cols, edge_vals);

    // S1 = spmm(x); g_X = x + 0.5*S1 + 0.25*spmm(S1)
    k_spmm<<<NN, 128>>>(x, 0);
    k_spmm<<<NN, 128>>>(x, 1);

    // fused sage + value/attn + retention weights -> h
    k_g1<<<MROWS/64, 256, SMEM_GEMM>>>(x, sage_b, attn_ln_g, attn_ln_b);

    // final lin + silu + LN -> out
    k_g2<<<MROWS/64, 256, SMEM_GEMM>>>(lin_b, ln_g, ln_b, out);
}